// round 9
// baseline (speedup 1.0000x reference)
#include <cuda_runtime.h>
#include <cstdint>

#define FNUM 50
#define DDIM 16
#define ADIM 32
#define NP   1225
#define NPAD 1232                // 77 tiles of 16
#define MT   77
#define TPB  256
#define ESTR 20                  // padded e-row stride (floats); keeps float4 alignment

typedef unsigned int u32;

// tf32 split: hi = x with low 13 mantissa bits zeroed (exact tf32), lo = x - hi
// (Sterbenz-exact; HW truncates the register to tf32, so no second mask needed).
__device__ __forceinline__ void split_mask(float x, u32& hi, u32& lo) {
    hi = __float_as_uint(x) & 0xFFFFE000u;
    lo = __float_as_uint(x - __uint_as_float(hi));
}
__device__ __forceinline__ void mma_tf32(float* c, const u32* a, const u32* b) {
    asm volatile(
        "mma.sync.aligned.m16n8k8.row.col.f32.tf32.tf32.f32 "
        "{%0,%1,%2,%3}, {%4,%5,%6,%7}, {%8,%9}, {%0,%1,%2,%3};"
        : "+f"(c[0]), "+f"(c[1]), "+f"(c[2]), "+f"(c[3])
        : "r"(a[0]), "r"(a[1]), "r"(a[2]), "r"(a[3]), "r"(b[0]), "r"(b[1]));
}

__global__ __launch_bounds__(TPB) void afm_kernel(
    const float* __restrict__ feat,   // [B, F, D]
    const float* __restrict__ Wg,     // [D, A] row-major
    const float* __restrict__ hg,     // [A]
    const float* __restrict__ pvg,    // [D]
    float* __restrict__ out)          // [B]
{
    __shared__ __align__(16) float s_e[FNUM * ESTR];
    __shared__ float s_score[NP];
    __shared__ float s_t[NP];
    __shared__ unsigned short s_pair[NPAD];   // row | (col<<8)
    __shared__ float s_red[24];

    const int tid  = threadIdx.x;
    const int b    = blockIdx.x;
    const int lane = tid & 31;
    const int wid  = tid >> 5;
    const int g    = lane >> 2;      // A/C row group, B col
    const int m    = lane & 3;       // thread-in-group

    // ---- SMEM fill: features (padded stride), packed triu table ----
    {
        const float* src = feat + (size_t)b * (FNUM * DDIM);
        #pragma unroll 1
        for (int i = tid; i < FNUM * DDIM; i += TPB) {
            int r = i >> 4, d = i & 15;
            s_e[r * ESTR + d] = src[i];
        }
    }
    if (tid < FNUM - 1) {
        int r    = tid;
        int base = r * (FNUM - 1) - (r * (r - 1)) / 2;
        int cnt  = FNUM - 1 - r;
        for (int k = 0; k < cnt; ++k)
            s_pair[base + k] = (unsigned short)(r | ((r + 1 + k) << 8));
    }
    if (tid < NPAD - NP) s_pair[NP + tid] = (unsigned short)(0 | (1 << 8));

    // ---- B fragments (registers), K-PERMUTED: frag slot (kt, j) of lane m
    //      holds W[mem_d][n] with mem_d = 4m + 2kt + j ----
    u32 bh[4][2][2], bl[4][2][2];
    #pragma unroll
    for (int nt = 0; nt < 4; ++nt) {
        const int n = nt * 8 + g;
        #pragma unroll
        for (int kt = 0; kt < 2; ++kt) {
            const int d0 = 4 * m + 2 * kt;
            split_mask(Wg[d0 * ADIM + n],       bh[nt][kt][0], bl[nt][kt][0]);
            split_mask(Wg[(d0 + 1) * ADIM + n], bh[nt][kt][1], bl[nt][kt][1]);
        }
    }
    // h slice for epilogue: cols nt*8 + 2m, +1  (N not permuted)
    float hreg[8];
    #pragma unroll
    for (int nt = 0; nt < 4; ++nt) {
        hreg[2 * nt]     = hg[nt * 8 + 2 * m];
        hreg[2 * nt + 1] = hg[nt * 8 + 2 * m + 1];
    }
    // p_vec slice (permuted = contiguous): d = 4m..4m+3
    const float4 pvr = *(const float4*)(pvg + 4 * m);
    __syncthreads();

    // ---- main loop: one M-tile (16 pairs) per warp-iteration ----
    #pragma unroll 1
    for (int mt = wid; mt < MT; mt += TPB / 32) {
        const int p0 = mt * 16 + g;
        const int p1 = p0 + 8;
        const unsigned pr0 = s_pair[p0];
        const unsigned pr1 = s_pair[p1];
        const int r0 = pr0 & 0xFF, q0 = pr0 >> 8;
        const int r1 = pr1 & 0xFF, q1 = pr1 >> 8;

        // vectorized e-row loads: this lane's 4 contiguous d = 4m..4m+3
        const float4 ea = *(const float4*)(s_e + r0 * ESTR + 4 * m);
        const float4 fa = *(const float4*)(s_e + q0 * ESTR + 4 * m);
        const float4 eb = *(const float4*)(s_e + r1 * ESTR + 4 * m);
        const float4 fb = *(const float4*)(s_e + q1 * ESTR + 4 * m);

        // raw products (memory d-order)
        float x0[4], x1[4];
        x0[0] = ea.x * fa.x;  x0[1] = ea.y * fa.y;
        x0[2] = ea.z * fa.z;  x0[3] = ea.w * fa.w;
        x1[0] = eb.x * fb.x;  x1[1] = eb.y * fb.y;
        x1[2] = eb.z * fb.z;  x1[3] = eb.w * fb.w;

        // A fragments, permuted: frag (kt, col m, j) <- x[2kt + j]
        // a0 = row p0 slot j0, a1 = row p1 slot j0, a2 = row p0 slot j1, a3 = row p1 slot j1
        u32 ah[2][4], al[2][4];
        split_mask(x0[0], ah[0][0], al[0][0]);
        split_mask(x1[0], ah[0][1], al[0][1]);
        split_mask(x0[1], ah[0][2], al[0][2]);
        split_mask(x1[1], ah[0][3], al[0][3]);
        split_mask(x0[2], ah[1][0], al[1][0]);
        split_mask(x1[2], ah[1][1], al[1][1]);
        split_mask(x0[3], ah[1][2], al[1][2]);
        split_mask(x1[3], ah[1][3], al[1][3]);

        float acc[4][4];
        #pragma unroll
        for (int nt = 0; nt < 4; ++nt) {
            acc[nt][0] = 0.f; acc[nt][1] = 0.f; acc[nt][2] = 0.f; acc[nt][3] = 0.f;
        }

        // 3-pass split product: hi*hi + hi*lo + lo*hi  (lo*lo ~2^-22, dropped)
        #pragma unroll
        for (int kt = 0; kt < 2; ++kt) {
            #pragma unroll
            for (int nt = 0; nt < 4; ++nt) mma_tf32(acc[nt], ah[kt], bh[nt][kt]);
            #pragma unroll
            for (int nt = 0; nt < 4; ++nt) mma_tf32(acc[nt], ah[kt], bl[nt][kt]);
            #pragma unroll
            for (int nt = 0; nt < 4; ++nt) mma_tf32(acc[nt], al[kt], bh[nt][kt]);
        }

        // scalar t partials (full fp32): this lane's d-slice is contiguous
        float t0 = x0[0] * pvr.x;
        t0 = fmaf(x0[1], pvr.y, t0);
        t0 = fmaf(x0[2], pvr.z, t0);
        t0 = fmaf(x0[3], pvr.w, t0);
        float t1 = x1[0] * pvr.x;
        t1 = fmaf(x1[1], pvr.y, t1);
        t1 = fmaf(x1[2], pvr.z, t1);
        t1 = fmaf(x1[3], pvr.w, t1);

        // epilogue: relu + h-dot
        float s0 = 0.f, s1 = 0.f;
        #pragma unroll
        for (int nt = 0; nt < 4; ++nt) {
            s0 = fmaf(fmaxf(acc[nt][0], 0.f), hreg[2 * nt],     s0);
            s0 = fmaf(fmaxf(acc[nt][1], 0.f), hreg[2 * nt + 1], s0);
            s1 = fmaf(fmaxf(acc[nt][2], 0.f), hreg[2 * nt],     s1);
            s1 = fmaf(fmaxf(acc[nt][3], 0.f), hreg[2 * nt + 1], s1);
        }

        // quad reductions across m
        s0 += __shfl_xor_sync(0xffffffffu, s0, 1);
        s0 += __shfl_xor_sync(0xffffffffu, s0, 2);
        s1 += __shfl_xor_sync(0xffffffffu, s1, 1);
        s1 += __shfl_xor_sync(0xffffffffu, s1, 2);
        t0 += __shfl_xor_sync(0xffffffffu, t0, 1);
        t0 += __shfl_xor_sync(0xffffffffu, t0, 2);
        t1 += __shfl_xor_sync(0xffffffffu, t1, 1);
        t1 += __shfl_xor_sync(0xffffffffu, t1, 2);

        if (m == 0) {
            if (p0 < NP) { s_score[p0] = s0; s_t[p0] = t0; }
            if (p1 < NP) { s_score[p1] = s1; s_t[p1] = t1; }
        }
    }

    __syncthreads();

    // ---- fused softmax reduction: out[b] = sum(e*t) / sum(e) ----
    float mx = -3.4e38f;
    for (int p = tid; p < NP; p += TPB) mx = fmaxf(mx, s_score[p]);
    #pragma unroll
    for (int o = 16; o > 0; o >>= 1) mx = fmaxf(mx, __shfl_xor_sync(0xffffffffu, mx, o));
    if (lane == 0) s_red[wid] = mx;
    __syncthreads();

    float mm = s_red[0];
    #pragma unroll
    for (int i = 1; i < 8; ++i) mm = fmaxf(mm, s_red[i]);

    float se = 0.f, st = 0.f;
    for (int p = tid; p < NP; p += TPB) {
        float e = __expf(s_score[p] - mm);
        se += e;
        st = fmaf(e, s_t[p], st);
    }
    #pragma unroll
    for (int o = 16; o > 0; o >>= 1) {
        se += __shfl_xor_sync(0xffffffffu, se, o);
        st += __shfl_xor_sync(0xffffffffu, st, o);
    }
    if (lane == 0) { s_red[8 + wid] = se; s_red[16 + wid] = st; }
    __syncthreads();

    if (tid == 0) {
        float SE = 0.f, ST = 0.f;
        #pragma unroll
        for (int i = 0; i < 8; ++i) { SE += s_red[8 + i]; ST += s_red[16 + i]; }
        out[b] = ST / SE;
    }
}

extern "C" void kernel_launch(void* const* d_in, const int* in_sizes, int n_in,
                              void* d_out, int out_size) {
    const float* feat = (const float*)d_in[0];   // [B, 50, 16]
    const float* W    = (const float*)d_in[1];   // [16, 32]
    const float* h    = (const float*)d_in[2];   // [32]
    const float* pv   = (const float*)d_in[3];   // [16]
    float* out        = (float*)d_out;           // [B, 1]

    const int B = in_sizes[0] / (FNUM * DDIM);   // 4096
    afm_kernel<<<B, TPB>>>(feat, W, h, pv, out);
}

// round 10
// speedup vs baseline: 1.3371x; 1.3371x over previous
#include <cuda_runtime.h>
#include <cstdint>

#define FNUM 50
#define DDIM 16
#define ADIM 32
#define NP   1225
#define NPAD 1232                // 77 tiles of 16
#define MT   77
#define TPB  256
#define ESTR 20                  // padded e-row stride (floats); float4-aligned

typedef unsigned int u32;

// Split x into bf16 hi + bf16 lo, two values packed per bf16x2 register.
// reg = {lo16 = bf16(x0), hi16 = bf16(x1)}  (MMA fragment order: even elem low).
__device__ __forceinline__ void split_bf16x2(float x0, float x1, u32& hi, u32& lo) {
    asm("cvt.rn.bf16x2.f32 %0, %1, %2;" : "=r"(hi) : "f"(x1), "f"(x0));
    float h0 = __uint_as_float(hi << 16);
    float h1 = __uint_as_float(hi & 0xFFFF0000u);
    float r0 = x0 - h0;
    float r1 = x1 - h1;
    asm("cvt.rn.bf16x2.f32 %0, %1, %2;" : "=r"(lo) : "f"(r1), "f"(r0));
}
__device__ __forceinline__ void mma_bf16(float* c, const u32* a, const u32* b) {
    asm volatile(
        "mma.sync.aligned.m16n8k16.row.col.f32.bf16.bf16.f32 "
        "{%0,%1,%2,%3}, {%4,%5,%6,%7}, {%8,%9}, {%0,%1,%2,%3};"
        : "+f"(c[0]), "+f"(c[1]), "+f"(c[2]), "+f"(c[3])
        : "r"(a[0]), "r"(a[1]), "r"(a[2]), "r"(a[3]), "r"(b[0]), "r"(b[1]));
}

__global__ __launch_bounds__(TPB) void afm_kernel(
    const float* __restrict__ feat,   // [B, F, D]
    const float* __restrict__ Wg,     // [D, A] row-major
    const float* __restrict__ hg,     // [A]
    const float* __restrict__ pvg,    // [D]
    float* __restrict__ out)          // [B]
{
    __shared__ __align__(16) float s_e[FNUM * ESTR];
    __shared__ float s_score[NP];
    __shared__ float s_t[NP];
    __shared__ unsigned short s_pair[NPAD];   // row | (col<<8)
    __shared__ float s_red[24];

    const int tid  = threadIdx.x;
    const int b    = blockIdx.x;
    const int lane = tid & 31;
    const int wid  = tid >> 5;
    const int g    = lane >> 2;      // A/C row group, B col
    const int m    = lane & 3;       // thread-in-group

    // ---- SMEM fill: features (padded stride), packed triu table ----
    {
        const float* src = feat + (size_t)b * (FNUM * DDIM);
        #pragma unroll 1
        for (int i = tid; i < FNUM * DDIM; i += TPB) {
            int r = i >> 4, d = i & 15;
            s_e[r * ESTR + d] = src[i];
        }
    }
    if (tid < FNUM - 1) {
        int r    = tid;
        int base = r * (FNUM - 1) - (r * (r - 1)) / 2;
        int cnt  = FNUM - 1 - r;
        for (int k = 0; k < cnt; ++k)
            s_pair[base + k] = (unsigned short)(r | ((r + 1 + k) << 8));
    }
    if (tid < NPAD - NP) s_pair[NP + tid] = (unsigned short)(0 | (1 << 8));

    // ---- B fragments (registers), K-permuted so this lane's memory d-slice
    //      is contiguous 4m..4m+3:
    //      b[nt][0] = {W[4m][n], W[4m+1][n]},  b[nt][1] = {W[4m+2][n], W[4m+3][n]}
    u32 bh[4][2], bl[4][2];
    #pragma unroll
    for (int nt = 0; nt < 4; ++nt) {
        const int n = nt * 8 + g;
        split_bf16x2(Wg[(4 * m)     * ADIM + n], Wg[(4 * m + 1) * ADIM + n],
                     bh[nt][0], bl[nt][0]);
        split_bf16x2(Wg[(4 * m + 2) * ADIM + n], Wg[(4 * m + 3) * ADIM + n],
                     bh[nt][1], bl[nt][1]);
    }
    // h slice for epilogue: cols nt*8 + 2m, +1  (N not permuted)
    float hreg[8];
    #pragma unroll
    for (int nt = 0; nt < 4; ++nt) {
        hreg[2 * nt]     = hg[nt * 8 + 2 * m];
        hreg[2 * nt + 1] = hg[nt * 8 + 2 * m + 1];
    }
    // p_vec slice (permuted = contiguous): d = 4m..4m+3
    const float4 pvr = *(const float4*)(pvg + 4 * m);
    __syncthreads();

    // ---- main loop: one M-tile (16 pairs) per warp-iteration ----
    #pragma unroll 1
    for (int mt = wid; mt < MT; mt += TPB / 32) {
        const int p0 = mt * 16 + g;
        const int p1 = p0 + 8;
        const unsigned pr0 = s_pair[p0];
        const unsigned pr1 = s_pair[p1];
        const int r0 = pr0 & 0xFF, q0 = pr0 >> 8;
        const int r1 = pr1 & 0xFF, q1 = pr1 >> 8;

        // vectorized e-row loads: this lane's 4 contiguous d = 4m..4m+3
        const float4 ea = *(const float4*)(s_e + r0 * ESTR + 4 * m);
        const float4 fa = *(const float4*)(s_e + q0 * ESTR + 4 * m);
        const float4 eb = *(const float4*)(s_e + r1 * ESTR + 4 * m);
        const float4 fb = *(const float4*)(s_e + q1 * ESTR + 4 * m);

        // raw products (memory d-order)
        float x0[4], x1[4];
        x0[0] = ea.x * fa.x;  x0[1] = ea.y * fa.y;
        x0[2] = ea.z * fa.z;  x0[3] = ea.w * fa.w;
        x1[0] = eb.x * fb.x;  x1[1] = eb.y * fb.y;
        x1[2] = eb.z * fb.z;  x1[3] = eb.w * fb.w;

        // A fragments m16n8k16 (bf16x2 regs):
        // a0 = row p0 k-lo, a1 = row p1 k-lo, a2 = row p0 k-hi, a3 = row p1 k-hi
        u32 ah[4], al[4];
        split_bf16x2(x0[0], x0[1], ah[0], al[0]);
        split_bf16x2(x1[0], x1[1], ah[1], al[1]);
        split_bf16x2(x0[2], x0[3], ah[2], al[2]);
        split_bf16x2(x1[2], x1[3], ah[3], al[3]);

        float acc[4][4];
        #pragma unroll
        for (int nt = 0; nt < 4; ++nt) {
            acc[nt][0] = 0.f; acc[nt][1] = 0.f; acc[nt][2] = 0.f; acc[nt][3] = 0.f;
        }

        // 3-pass split product: hi*hi + hi*lo + lo*hi  (lo*lo ~2^-18, dropped)
        #pragma unroll
        for (int nt = 0; nt < 4; ++nt) mma_bf16(acc[nt], ah, bh[nt]);
        #pragma unroll
        for (int nt = 0; nt < 4; ++nt) mma_bf16(acc[nt], ah, bl[nt]);
        #pragma unroll
        for (int nt = 0; nt < 4; ++nt) mma_bf16(acc[nt], al, bh[nt]);

        // scalar t partials (full fp32)
        float t0 = x0[0] * pvr.x;
        t0 = fmaf(x0[1], pvr.y, t0);
        t0 = fmaf(x0[2], pvr.z, t0);
        t0 = fmaf(x0[3], pvr.w, t0);
        float t1 = x1[0] * pvr.x;
        t1 = fmaf(x1[1], pvr.y, t1);
        t1 = fmaf(x1[2], pvr.z, t1);
        t1 = fmaf(x1[3], pvr.w, t1);

        // epilogue: relu + h-dot
        float s0 = 0.f, s1 = 0.f;
        #pragma unroll
        for (int nt = 0; nt < 4; ++nt) {
            s0 = fmaf(fmaxf(acc[nt][0], 0.f), hreg[2 * nt],     s0);
            s0 = fmaf(fmaxf(acc[nt][1], 0.f), hreg[2 * nt + 1], s0);
            s1 = fmaf(fmaxf(acc[nt][2], 0.f), hreg[2 * nt],     s1);
            s1 = fmaf(fmaxf(acc[nt][3], 0.f), hreg[2 * nt + 1], s1);
        }

        // quad reductions across m
        s0 += __shfl_xor_sync(0xffffffffu, s0, 1);
        s0 += __shfl_xor_sync(0xffffffffu, s0, 2);
        s1 += __shfl_xor_sync(0xffffffffu, s1, 1);
        s1 += __shfl_xor_sync(0xffffffffu, s1, 2);
        t0 += __shfl_xor_sync(0xffffffffu, t0, 1);
        t0 += __shfl_xor_sync(0xffffffffu, t0, 2);
        t1 += __shfl_xor_sync(0xffffffffu, t1, 1);
        t1 += __shfl_xor_sync(0xffffffffu, t1, 2);

        if (m == 0) {
            if (p0 < NP) { s_score[p0] = s0; s_t[p0] = t0; }
            if (p1 < NP) { s_score[p1] = s1; s_t[p1] = t1; }
        }
    }

    __syncthreads();

    // ---- fused softmax reduction: out[b] = sum(e*t) / sum(e) ----
    float mx = -3.4e38f;
    for (int p = tid; p < NP; p += TPB) mx = fmaxf(mx, s_score[p]);
    #pragma unroll
    for (int o = 16; o > 0; o >>= 1) mx = fmaxf(mx, __shfl_xor_sync(0xffffffffu, mx, o));
    if (lane == 0) s_red[wid] = mx;
    __syncthreads();

    float mm = s_red[0];
    #pragma unroll
    for (int i = 1; i < 8; ++i) mm = fmaxf(mm, s_red[i]);

    float se = 0.f, st = 0.f;
    for (int p = tid; p < NP; p += TPB) {
        float e = __expf(s_score[p] - mm);
        se += e;
        st = fmaf(e, s_t[p], st);
    }
    #pragma unroll
    for (int o = 16; o > 0; o >>= 1) {
        se += __shfl_xor_sync(0xffffffffu, se, o);
        st += __shfl_xor_sync(0xffffffffu, st, o);
    }
    if (lane == 0) { s_red[8 + wid] = se; s_red[16 + wid] = st; }
    __syncthreads();

    if (tid == 0) {
        float SE = 0.f, ST = 0.f;
        #pragma unroll
        for (int i = 0; i < 8; ++i) { SE += s_red[8 + i]; ST += s_red[16 + i]; }
        out[b] = ST / SE;
    }
}

extern "C" void kernel_launch(void* const* d_in, const int* in_sizes, int n_in,
                              void* d_out, int out_size) {
    const float* feat = (const float*)d_in[0];   // [B, 50, 16]
    const float* W    = (const float*)d_in[1];   // [16, 32]
    const float* h    = (const float*)d_in[2];   // [32]
    const float* pv   = (const float*)d_in[3];   // [16]
    float* out        = (float*)d_out;           // [B, 1]

    const int B = in_sizes[0] / (FNUM * DDIM);   // 4096
    afm_kernel<<<B, TPB>>>(feat, W, h, pv, out);
}